// round 15
// baseline (speedup 1.0000x reference)
#include <cuda_runtime.h>
#include <cuda_fp16.h>
#include <cstdint>

#define B_    32
#define D_    256
#define HW_   4096
#define K_    1024
#define NROWS (B_ * HW_)
#define TENSOR_ELEMS (B_ * D_ * HW_)
#define THRESH 1.5e-4f

__device__ __half g_eh[K_ * D_];     // fp16 of (-2*E), k-major rows
__device__ float g_enorm[K_];
__device__ int   g_idx[NROWS];
__device__ float g_bsum[1024];
__device__ int   g_fixn;
__device__ int   g_fixlist[NROWS];

// ---------------- PTX helpers (plain sm_80-level, no 'a' features) ----------
__device__ __forceinline__ uint32_t smem_u32(const void* p) {
    uint32_t a;
    asm("{ .reg .u64 t; cvta.to.shared.u64 t, %1; cvt.u32.u64 %0, t; }" : "=r"(a) : "l"(p));
    return a;
}
__device__ __forceinline__ void cp16(uint32_t dst, const void* src) {
    asm volatile("cp.async.cg.shared.global [%0], [%1], 16;" :: "r"(dst), "l"(src) : "memory");
}
#define CP_COMMIT() asm volatile("cp.async.commit_group;" ::: "memory")
#define CP_WAIT0()  asm volatile("cp.async.wait_group 0;" ::: "memory")

__device__ __forceinline__ void ldsm4(uint32_t* r, uint32_t addr) {
    asm volatile("ldmatrix.sync.aligned.m8n8.x4.shared.b16 {%0,%1,%2,%3}, [%4];"
                 : "=r"(r[0]), "=r"(r[1]), "=r"(r[2]), "=r"(r[3]) : "r"(addr));
}
__device__ __forceinline__ void mma16816(float* c, const uint32_t* a, const uint32_t* b) {
    asm volatile("mma.sync.aligned.m16n8k16.row.col.f32.f16.f16.f32 "
                 "{%0,%1,%2,%3}, {%4,%5,%6,%7}, {%8,%9}, {%0,%1,%2,%3};"
                 : "+f"(c[0]), "+f"(c[1]), "+f"(c[2]), "+f"(c[3])
                 : "r"(a[0]), "r"(a[1]), "r"(a[2]), "r"(a[3]), "r"(b[0]), "r"(b[1]));
}

// smem layout (bytes): X 32K | B 2x32K | Se 4K | red 3K  -> 103 KB, occ 2
#define SM_XHI   0
#define SM_E     32768
#define SM_SE    98304
#define SM_RED   102400
#define SM_TOTAL 105472

// ---------------- dummy: shifts argmin into ncu's capture window ------------
__global__ void dummy_kernel() {
    if (blockIdx.x > 1000) g_bsum[0] = 0.f;   // never true (grid = 1)
}

// ---------------- prep: fp16 of (-2E), ||e||^2 ------------------------------
__global__ void prep_kernel(const float* __restrict__ emb) {
    int k = blockIdx.x, d = threadIdx.x;
    g_eh[k * D_ + d] = __float2half(-2.0f * emb[k * D_ + d]);
    if (d == 0) {
        const float* r = emb + (size_t)k * D_;
        float s = 0.f;
        for (int i = 0; i < D_; ++i) { float v = r[i]; s = fmaf(v, v, s); }
        g_enorm[k] = s;
        if (k == 0) g_fixn = 0;
    }
}

// stage one 256-code x 64-d fp16 tile into a 32KB buffer (8 cp16/thread)
__device__ __forceinline__ void stage_B256(uint32_t ebase, const __half* Eptr, int tid) {
    #pragma unroll
    for (int i = 0; i < 8; ++i) {
        int idx = tid + i * 256;                   // 0..2047
        int r = idx >> 3, s = idx & 7;             // r: code row 0..255, s: 8-half col
        uint32_t dst = (uint32_t)((r >> 3) * 1024 + (r & 7) * 128 +
                                  ((s * 16) ^ ((r & 7) << 4)));
        cp16(ebase + dst, Eptr + (size_t)r * D_ + s * 8);
    }
    CP_COMMIT();
}

// ---------------- HMMA argmin: 64 pixels/CTA, warp tile 32x64, occ 2 --------
__global__ __launch_bounds__(256, 2)
void argmin_kernel(const float* __restrict__ x) {
    extern __shared__ char smem[];
    const uint32_t sb = smem_u32(smem);
    float* sSe  = (float*)(smem + SM_SE);
    float* red  = (float*)(smem + SM_RED);

    const int tid  = threadIdx.x;
    const int lane = tid & 31;
    const int w    = tid >> 5;
    const int wm   = w & 1;        // pixel half (rows 0-31 / 32-63)
    const int wn   = w >> 1;       // code group (4 x 64 within a 256-code pass)
    const int b    = blockIdx.x >> 6;
    const int c0   = (blockIdx.x & 63) * 64;

    for (int i = tid; i < K_; i += 256) sSe[i] = g_enorm[i];

    // prefetch seg0 (pass0, dchunk0) into buffer 0
    stage_B256(sb + SM_E, g_eh, tid);

    // stage X tile [64 pixels x 256 d] fp16, SW128 K-major (4 x 8KB d-chunks)
    {
        const int p = tid & 63, half = tid >> 6;   // half in 0..3: 64 d each
        const float* xb = x + (size_t)b * (D_ * HW_) + c0 + p;
        const uint32_t rowbase = (uint32_t)((p >> 3) * 1024 + (p & 7) * 128);
        const uint32_t rx = (uint32_t)((p & 7) << 4);
        for (int d0 = half * 64; d0 < half * 64 + 64; d0 += 8) {
            float v[8];
            #pragma unroll
            for (int i = 0; i < 8; ++i) v[i] = xb[(size_t)(d0 + i) * HW_];
            uint32_t hp[4];
            #pragma unroll
            for (int i = 0; i < 4; ++i) {
                __half h0 = __float2half(v[2*i]);
                __half h1 = __float2half(v[2*i+1]);
                hp[i] = (uint32_t)__half_as_ushort(h0) |
                        ((uint32_t)__half_as_ushort(h1) << 16);
            }
            uint32_t off = (uint32_t)(d0 >> 6) * 8192u + rowbase +
                           (((uint32_t)(d0 & 63) * 2u) ^ rx);
            *(uint4*)(smem + SM_XHI + off) = make_uint4(hp[0], hp[1], hp[2], hp[3]);
        }
    }

    // A-side ldmatrix constants (2 x 16x16 tiles over this warp's 32 rows)
    uint32_t aOff[2], aXor[2];
    #pragma unroll
    for (int mt = 0; mt < 2; ++mt) {
        int r = wm * 32 + mt * 16 + (lane & 7) + ((lane >> 3) & 1) * 8;
        aOff[mt] = (uint32_t)((r >> 3) * 1024 + (r & 7) * 128);
        aXor[mt] = (uint32_t)((r & 7) << 4);
    }
    const uint32_t adB = (lane >> 4) ? 16u : 0u;
    // B-side: 4 paired ldsm4 -> 8 n-tiles of 8 codes (warp covers 64 codes)
    uint32_t bpOff[4], bpXor[4];
    #pragma unroll
    for (int p = 0; p < 4; ++p) {
        int n = wn * 64 + p * 16 + ((lane >> 4) << 3) + (lane & 7);
        bpOff[p] = (uint32_t)((n >> 3) * 1024 + (n & 7) * 128);
        bpXor[p] = (uint32_t)((n & 7) << 4);
    }
    const uint32_t kB = (uint32_t)(((lane >> 3) & 1) << 4);

    float m1r[4], m2r[4]; int i1r[4];
    #pragma unroll
    for (int s = 0; s < 4; ++s) { m1r[s] = 3.4e38f; m2r[s] = 3.4e38f; i1r[s] = 0; }

    float acc[2][8][4];

    for (int seg = 0; seg < 16; ++seg) {        // seg = pass*4 + dchunk
        const int ch = seg & 3;
        // Hazard-safe single barrier: WAIT0 completes the group staged last
        // seg; the barrier (a) makes it visible to all warps and (b) orders
        // all of last seg's reads BEFORE this seg's cp.async overwrites.
        CP_WAIT0();
        __syncthreads();
        if (seg < 15) {
            const int ns = seg + 1;
            stage_B256(sb + SM_E + (uint32_t)(ns & 1) * 32768u,
                       g_eh + (size_t)(ns >> 2) * 256 * D_ + (ns & 3) * 64, tid);
        }

        if (ch == 0) {
            #pragma unroll
            for (int mt = 0; mt < 2; ++mt)
                #pragma unroll
                for (int nt = 0; nt < 8; ++nt)
                    #pragma unroll
                    for (int q = 0; q < 4; ++q) acc[mt][nt][q] = 0.f;
        }

        const uint32_t eh  = sb + SM_E + (uint32_t)(seg & 1) * 32768u;
        const uint32_t xco = (uint32_t)ch * 8192u;

        #pragma unroll
        for (int ks = 0; ks < 4; ++ks) {
            const uint32_t ksl = (uint32_t)ks * 32u;
            const uint32_t dA  = ksl + adB;
            uint32_t bh[8][2], ah[2][4];
            #pragma unroll
            for (int p = 0; p < 4; ++p) {
                uint32_t r4[4];
                ldsm4(r4, eh + bpOff[p] + ((ksl + kB) ^ bpXor[p]));
                bh[2*p][0] = r4[0]; bh[2*p][1] = r4[1];
                bh[2*p+1][0] = r4[2]; bh[2*p+1][1] = r4[3];
            }
            #pragma unroll
            for (int mt = 0; mt < 2; ++mt)
                ldsm4(ah[mt], sb + SM_XHI + xco + aOff[mt] + (dA ^ aXor[mt]));
            #pragma unroll
            for (int mt = 0; mt < 2; ++mt)
                #pragma unroll
                for (int nt = 0; nt < 8; ++nt)
                    mma16816(acc[mt][nt], ah[mt], bh[nt]);
        }

        if (ch == 3) {
            // fold scores: s = Se + dot (Sx dropped: rank-invariant; fixup
            // recomputes the exact reference formula for near-ties)
            const int pass = seg >> 2;
            const int cbase = pass * 256 + wn * 64 + 2 * (lane & 3);
            #pragma unroll
            for (int nt = 0; nt < 8; ++nt) {
                const int code0 = cbase + nt * 8;
                const float se0 = sSe[code0], se1 = sSe[code0 + 1];
                #pragma unroll
                for (int mt = 0; mt < 2; ++mt) {
                    const int s0 = mt * 2, s1 = mt * 2 + 1;
                    float v;
                    v = se0 + acc[mt][nt][0];
                    if (v < m1r[s0]) { m2r[s0] = m1r[s0]; m1r[s0] = v; i1r[s0] = code0; }
                    else if (v < m2r[s0]) m2r[s0] = v;
                    v = se1 + acc[mt][nt][1];
                    if (v < m1r[s0]) { m2r[s0] = m1r[s0]; m1r[s0] = v; i1r[s0] = code0 + 1; }
                    else if (v < m2r[s0]) m2r[s0] = v;
                    v = se0 + acc[mt][nt][2];
                    if (v < m1r[s1]) { m2r[s1] = m1r[s1]; m1r[s1] = v; i1r[s1] = code0; }
                    else if (v < m2r[s1]) m2r[s1] = v;
                    v = se1 + acc[mt][nt][3];
                    if (v < m1r[s1]) { m2r[s1] = m1r[s1]; m1r[s1] = v; i1r[s1] = code0 + 1; }
                    else if (v < m2r[s1]) m2r[s1] = v;
                }
            }
        }
    }

    __syncthreads();
    #pragma unroll
    for (int s = 0; s < 4; ++s) {
        float a1 = m1r[s], a2 = m2r[s]; int ai = i1r[s];
        #pragma unroll
        for (int ofs = 1; ofs <= 2; ofs <<= 1) {
            float v1 = __shfl_xor_sync(0xffffffffu, a1, ofs);
            float v2 = __shfl_xor_sync(0xffffffffu, a2, ofs);
            int   vi = __shfl_xor_sync(0xffffffffu, ai, ofs);
            if (v1 < a1 || (v1 == a1 && vi < ai)) { a2 = fminf(a1, v2); a1 = v1; ai = vi; }
            else                                  { a2 = fminf(a2, v1); }
        }
        if ((lane & 3) == 0) {
            int pix = wm * 32 + (s >> 1) * 16 + (lane >> 2) + (s & 1) * 8;
            red[(pix * 4 + wn) * 3 + 0] = a1;
            red[(pix * 4 + wn) * 3 + 1] = a2;
            red[(pix * 4 + wn) * 3 + 2] = __int_as_float(ai);
        }
    }
    __syncthreads();

    if (tid < 64) {
        float a1 = red[(tid * 4) * 3], a2 = red[(tid * 4) * 3 + 1];
        int   ai = __float_as_int(red[(tid * 4) * 3 + 2]);
        #pragma unroll
        for (int q = 1; q < 4; ++q) {
            float v1 = red[(tid * 4 + q) * 3], v2 = red[(tid * 4 + q) * 3 + 1];
            int   vi = __float_as_int(red[(tid * 4 + q) * 3 + 2]);
            if (v1 < a1 || (v1 == a1 && vi < ai)) { a2 = fminf(a1, v2); a1 = v1; ai = vi; }
            else                                  { a2 = fminf(a2, v1); }
        }
        const int row = b * HW_ + c0 + tid;
        g_idx[row] = ai;
        if (a2 - a1 < THRESH) {
            int pos = atomicAdd(&g_fixn, 1);
            g_fixlist[pos] = row;
        }
    }
}

// ---------------- exact-fp32 fixup v2: 2 rows/thread, d-split x2 ------------
#define FX_SX   0
#define FX_ED   16448
#define FX_SSX  (FX_ED + 69632)
#define FX_ROWS (FX_SSX + 64)
#define FX_TOTAL (FX_ROWS + 64)

__global__ __launch_bounds__(256)
void fixup_kernel(const float* __restrict__ x, const float* __restrict__ emb) {
    extern __shared__ char fsm[];
    float* sx  = (float*)(fsm + FX_SX);    // [16][257]
    float* ed  = (float*)(fsm + FX_ED);    // [256][68]
    float* sSx = (float*)(fsm + FX_SSX);   // [16]
    int*   rws = (int*)(fsm + FX_ROWS);    // [16]

    const int n    = g_fixn;
    const int tid  = threadIdx.x;
    const int lane = tid & 31;
    const int w    = tid >> 5;
    const int tc   = lane & 15;            // 4 codes per cb
    const int dh   = lane >> 4;            // d half: [0,128) or [128,256)
    const int rA   = w, rB = w + 8;        // this warp's two rows
    const int d0   = dh * 128;

    for (int base = blockIdx.x * 16; base < n; base += gridDim.x * 16) {
        if (tid < 16) rws[tid] = (base + tid < n) ? g_fixlist[base + tid] : -1;
        __syncthreads();
        // stage x rows (coalesced over pixels via strided d walk)
        for (int i = tid; i < 16 * D_; i += 256) {
            int rr = i >> 8, d = i & 255;
            int row = rws[rr];
            int row_c = (row < 0) ? 0 : row;
            int bb = row_c >> 12, pix = row_c & 4095;
            sx[rr * 257 + d] = x[(size_t)bb * (D_ * HW_) + (size_t)d * HW_ + pix];
        }
        __syncthreads();
        if (tid < 16) {   // ascending serial Sx (reference order)
            float s = 0.f;
            const float* xr = sx + tid * 257;
            for (int d = 0; d < D_; ++d) { float v = xr[d]; s = fmaf(v, v, s); }
            sSx[tid] = s;
        }

        float mA = 3.4e38f, mB = 3.4e38f;
        int   biA = 0, biB = 0;

        for (int cb = 0; cb < 16; ++cb) {
            __syncthreads();   // also covers the sSx writes on cb==0
            {   // stage 64 codes transposed: ed[d][cc]
                int cc = tid >> 2, dseg = (tid & 3) * 64;
                const float* er = emb + (size_t)(cb * 64 + cc) * D_ + dseg;
                for (int i = 0; i < 64; i += 4) {
                    float4 v = *(const float4*)(er + i);
                    ed[(dseg + i)     * 68 + cc] = v.x;
                    ed[(dseg + i + 1) * 68 + cc] = v.y;
                    ed[(dseg + i + 2) * 68 + cc] = v.z;
                    ed[(dseg + i + 3) * 68 + cc] = v.w;
                }
            }
            __syncthreads();
            // serial ascending fmaf over this thread's 128-d half, 2 rows x 4 codes
            float a0A = 0.f, a1A = 0.f, a2A = 0.f, a3A = 0.f;
            float a0B = 0.f, a1B = 0.f, a2B = 0.f, a3B = 0.f;
            const float* xrA = sx + rA * 257 + d0;
            const float* xrB = sx + rB * 257 + d0;
            const float* edp = ed + d0 * 68 + tc * 4;
            for (int d = 0; d < 128; ++d) {
                float4 ev = *(const float4*)(edp + d * 68);
                float xa = xrA[d], xb = xrB[d];
                a0A = fmaf(ev.x, xa, a0A); a1A = fmaf(ev.y, xa, a1A);
                a2A = fmaf(ev.z, xa, a2A); a3A = fmaf(ev.w, xa, a3A);
                a0B = fmaf(ev.x, xb, a0B); a1B = fmaf(ev.y, xb, a1B);
                a2B = fmaf(ev.z, xb, a2B); a3B = fmaf(ev.w, xb, a3B);
            }
            // combine the two d-halves (lane ^ 16 holds the partner partial)
            float pA[4] = {a0A, a1A, a2A, a3A};
            float pB[4] = {a0B, a1B, a2B, a3B};
            const float SxA = sSx[rA], SxB = sSx[rB];
            #pragma unroll
            for (int j = 0; j < 4; ++j) {
                float tA = pA[j] + __shfl_xor_sync(0xffffffffu, pA[j], 16);
                float tB = pB[j] + __shfl_xor_sync(0xffffffffu, pB[j], 16);
                int code = cb * 64 + tc * 4 + j;
                float en = g_enorm[code];
                float vA = fmaf(-2.f, tA, SxA + en);   // reference formula
                float vB = fmaf(-2.f, tB, SxB + en);
                if (vA < mA) { mA = vA; biA = code; }
                if (vB < mB) { mB = vB; biB = code; }
            }
        }
        // full-warp argmin reduce (dh halves hold identical values: harmless)
        #pragma unroll
        for (int ofs = 1; ofs <= 16; ofs <<= 1) {
            float ovA = __shfl_xor_sync(0xffffffffu, mA, ofs);
            int   oiA = __shfl_xor_sync(0xffffffffu, biA, ofs);
            if (ovA < mA || (ovA == mA && oiA < biA)) { mA = ovA; biA = oiA; }
            float ovB = __shfl_xor_sync(0xffffffffu, mB, ofs);
            int   oiB = __shfl_xor_sync(0xffffffffu, biB, ofs);
            if (ovB < mB || (ovB == mB && oiB < biB)) { mB = ovB; biB = oiB; }
        }
        if (lane == 0) {
            if (rws[rA] >= 0) g_idx[rws[rA]] = biA;
            if (rws[rB] >= 0) g_idx[rws[rB]] = biB;
        }
        __syncthreads();
    }
}

// ---------------- gather: 64-d chunks, MLP-8 batched loads, scalar stores ----
#define G_SIDX  0
#define G_WS    512
#define G_ET    1024                       // et[d][pixel], 64 x 132 floats
#define G_TOTAL (G_ET + 64 * 132 * 4)

__global__ __launch_bounds__(256)
void gather_kernel(const float* __restrict__ x, const float* __restrict__ emb,
                   float* __restrict__ outT) {
    extern __shared__ char gsm[];
    int*   sidx = (int*)(gsm + G_SIDX);
    float* ws   = (float*)(gsm + G_WS);
    float* et   = (float*)(gsm + G_ET);

    const int tid = threadIdx.x;
    const int b   = blockIdx.y;
    const int c0  = blockIdx.x * 128;
    if (tid < 128) sidx[tid] = g_idx[b * HW_ + c0 + tid];
    __syncthreads();

    const int pg = (tid & 31) * 4;     // 4-pixel group within warp
    const int dg = tid >> 5;           // warp -> 8 d rows per 64-d chunk
    float lsum = 0.f;

    for (int d0 = 0; d0 < D_; d0 += 64) {
        if (d0) __syncthreads();
        #pragma unroll
        for (int i = 0; i < 8; ++i) {
            int idx = tid + i * 256;
            int p = idx & 127, f4 = idx >> 7;
            float4 v = *(const float4*)(emb + (size_t)sidx[p] * D_ + d0 + f4 * 4);
            et[(f4 * 4 + 0) * 132 + p] = v.x;
            et[(f4 * 4 + 1) * 132 + p] = v.y;
            et[(f4 * 4 + 2) * 132 + p] = v.z;
            et[(f4 * 4 + 3) * 132 + p] = v.w;
        }
        __syncthreads();
        // batch ALL 8 x loads first (MLP=8), then compute + scalar stores
        const size_t base0 = (size_t)b * (D_ * HW_) + (size_t)(d0 + dg * 8) * HW_ + c0 + pg;
        float4 xv[8];
        #pragma unroll
        for (int j = 0; j < 8; ++j)
            xv[j] = *(const float4*)(x + base0 + (size_t)j * HW_);
        #pragma unroll
        for (int j = 0; j < 8; ++j) {
            float4 q = *(const float4*)(et + (dg * 8 + j) * 132 + pg);
            float dx0 = q.x - xv[j].x, dx1 = q.y - xv[j].y;
            float dx2 = q.z - xv[j].z, dx3 = q.w - xv[j].w;
            lsum = fmaf(dx0, dx0, lsum); lsum = fmaf(dx1, dx1, lsum);
            lsum = fmaf(dx2, dx2, lsum); lsum = fmaf(dx3, dx3, lsum);
            float* op = outT + base0 + (size_t)j * HW_;   // 4B-aligned: scalar STG
            op[0] = xv[j].x + dx0;                        // STE: fl(x + fl(q - x))
            op[1] = xv[j].y + dx1;
            op[2] = xv[j].z + dx2;
            op[3] = xv[j].w + dx3;
        }
    }
    #pragma unroll
    for (int o = 16; o; o >>= 1) lsum += __shfl_down_sync(0xffffffffu, lsum, o);
    if ((tid & 31) == 0) ws[tid >> 5] = lsum;
    __syncthreads();
    if (tid == 0) {
        float s = 0.f;
        #pragma unroll
        for (int i = 0; i < 8; ++i) s += ws[i];
        g_bsum[blockIdx.y * 32 + blockIdx.x] = s;
    }
}

// ---------------- loss finalize --------------------------------------------
__global__ void finalize_kernel(const float* beta, float* out) {
    __shared__ float sh[256];
    int tid = threadIdx.x;
    float s = 0.f;
    for (int i = tid; i < 1024; i += 256) s += g_bsum[i];
    sh[tid] = s; __syncthreads();
    for (int o = 128; o; o >>= 1) {
        if (tid < o) sh[tid] += sh[tid + o];
        __syncthreads();
    }
    if (tid == 0) {
        float bv = 0.25f;
        if (beta) {
            float f = *beta;
            if (f > 0.0f && f < 100.0f) bv = f;
            else {
                double dv = *(const double*)beta;
                if (dv > 0.0 && dv < 100.0) bv = (float)dv;
            }
        }
        out[0] = (1.0f + bv) * (sh[0] / 33554432.0f);
    }
}

// ---------------------------------------------------------------------------
extern "C" void kernel_launch(void* const* d_in, const int* in_sizes, int n_in,
                              void* d_out, int out_size) {
    (void)in_sizes;
    const float* x    = (const float*)d_in[0];
    const float* emb  = (const float*)d_in[1];
    const float* beta = (n_in > 2) ? (const float*)d_in[2] : nullptr;
    float* out = (float*)d_out;

    int off = out_size - TENSOR_ELEMS;
    if (off < 0) off = 0;

    cudaFuncSetAttribute(argmin_kernel,
                         cudaFuncAttributeMaxDynamicSharedMemorySize, SM_TOTAL);
    cudaFuncSetAttribute(fixup_kernel,
                         cudaFuncAttributeMaxDynamicSharedMemorySize, FX_TOTAL);
    cudaFuncSetAttribute(gather_kernel,
                         cudaFuncAttributeMaxDynamicSharedMemorySize, G_TOTAL);

    prep_kernel<<<K_, 256>>>(emb);
    dummy_kernel<<<1, 32>>>();              // keep ncu window on argmin
    dummy_kernel<<<1, 32>>>();
    argmin_kernel<<<2048, 256, SM_TOTAL>>>(x);
    fixup_kernel<<<256, 256, FX_TOTAL>>>(x, emb);
    gather_kernel<<<dim3(32, 32), 256, G_TOTAL>>>(x, emb, out + off);
    if (off >= 1) finalize_kernel<<<1, 256>>>(beta, out);
}

// round 16
// speedup vs baseline: 1.5687x; 1.5687x over previous
#include <cuda_runtime.h>
#include <cuda_fp16.h>
#include <cstdint>

#define B_    32
#define D_    256
#define HW_   4096
#define K_    1024
#define NROWS (B_ * HW_)
#define TENSOR_ELEMS (B_ * D_ * HW_)
#define THRESH 1.5e-4f

__device__ __half g_eh[K_ * D_];     // fp16 of (-2*E), k-major rows
__device__ float g_enorm[K_];
__device__ int   g_idx[NROWS];
__device__ float g_bsum[1024];
__device__ int   g_fixn;
__device__ int   g_fixlist[NROWS];

// ---------------- PTX helpers (plain sm_80-level, no 'a' features) ----------
__device__ __forceinline__ uint32_t smem_u32(const void* p) {
    uint32_t a;
    asm("{ .reg .u64 t; cvta.to.shared.u64 t, %1; cvt.u32.u64 %0, t; }" : "=r"(a) : "l"(p));
    return a;
}
__device__ __forceinline__ void cp16(uint32_t dst, const void* src) {
    asm volatile("cp.async.cg.shared.global [%0], [%1], 16;" :: "r"(dst), "l"(src) : "memory");
}
#define CP_COMMIT() asm volatile("cp.async.commit_group;" ::: "memory")
#define CP_WAIT0()  asm volatile("cp.async.wait_group 0;" ::: "memory")

__device__ __forceinline__ void ldsm4(uint32_t* r, uint32_t addr) {
    asm volatile("ldmatrix.sync.aligned.m8n8.x4.shared.b16 {%0,%1,%2,%3}, [%4];"
                 : "=r"(r[0]), "=r"(r[1]), "=r"(r[2]), "=r"(r[3]) : "r"(addr));
}
__device__ __forceinline__ void mma16816(float* c, const uint32_t* a, const uint32_t* b) {
    asm volatile("mma.sync.aligned.m16n8k16.row.col.f32.f16.f16.f32 "
                 "{%0,%1,%2,%3}, {%4,%5,%6,%7}, {%8,%9}, {%0,%1,%2,%3};"
                 : "+f"(c[0]), "+f"(c[1]), "+f"(c[2]), "+f"(c[3])
                 : "r"(a[0]), "r"(a[1]), "r"(a[2]), "r"(a[3]), "r"(b[0]), "r"(b[1]));
}

// smem layout (bytes): X 32K | B 2x32K | Se 4K | red 3K  -> 103 KB, occ 2
#define SM_XHI   0
#define SM_E     32768
#define SM_SE    98304
#define SM_RED   102400
#define SM_TOTAL 105472

// ---------------- dummy: shifts argmin into ncu's capture window ------------
__global__ void dummy_kernel() {
    if (blockIdx.x > 1000) g_bsum[0] = 0.f;   // never true (grid = 1)
}

// ---------------- prep: fp16 of (-2E), ||e||^2 ------------------------------
__global__ void prep_kernel(const float* __restrict__ emb) {
    int k = blockIdx.x, d = threadIdx.x;
    g_eh[k * D_ + d] = __float2half(-2.0f * emb[k * D_ + d]);
    if (d == 0) {
        const float* r = emb + (size_t)k * D_;
        float s = 0.f;
        for (int i = 0; i < D_; ++i) { float v = r[i]; s = fmaf(v, v, s); }
        g_enorm[k] = s;
        if (k == 0) g_fixn = 0;
    }
}

// stage one 256-code x 64-d fp16 tile into a 32KB buffer (8 cp16/thread)
__device__ __forceinline__ void stage_B256(uint32_t ebase, const __half* Eptr, int tid) {
    #pragma unroll
    for (int i = 0; i < 8; ++i) {
        int idx = tid + i * 256;                   // 0..2047
        int r = idx >> 3, s = idx & 7;             // r: code row 0..255, s: 8-half col
        uint32_t dst = (uint32_t)((r >> 3) * 1024 + (r & 7) * 128 +
                                  ((s * 16) ^ ((r & 7) << 4)));
        cp16(ebase + dst, Eptr + (size_t)r * D_ + s * 8);
    }
    CP_COMMIT();
}

// ---------------- HMMA argmin: 64 pixels/CTA, warp tile 32x64, occ 2 --------
__global__ __launch_bounds__(256, 2)
void argmin_kernel(const float* __restrict__ x) {
    extern __shared__ char smem[];
    const uint32_t sb = smem_u32(smem);
    float* sSe  = (float*)(smem + SM_SE);
    float* red  = (float*)(smem + SM_RED);

    const int tid  = threadIdx.x;
    const int lane = tid & 31;
    const int w    = tid >> 5;
    const int wm   = w & 1;        // pixel half (rows 0-31 / 32-63)
    const int wn   = w >> 1;       // code group (4 x 64 within a 256-code pass)
    const int b    = blockIdx.x >> 6;
    const int c0   = (blockIdx.x & 63) * 64;

    for (int i = tid; i < K_; i += 256) sSe[i] = g_enorm[i];

    // prefetch seg0 (pass0, dchunk0) into buffer 0
    stage_B256(sb + SM_E, g_eh, tid);

    // stage X tile [64 pixels x 256 d] fp16, SW128 K-major (4 x 8KB d-chunks)
    {
        const int p = tid & 63, half = tid >> 6;   // half in 0..3: 64 d each
        const float* xb = x + (size_t)b * (D_ * HW_) + c0 + p;
        const uint32_t rowbase = (uint32_t)((p >> 3) * 1024 + (p & 7) * 128);
        const uint32_t rx = (uint32_t)((p & 7) << 4);
        for (int d0 = half * 64; d0 < half * 64 + 64; d0 += 8) {
            float v[8];
            #pragma unroll
            for (int i = 0; i < 8; ++i) v[i] = xb[(size_t)(d0 + i) * HW_];
            uint32_t hp[4];
            #pragma unroll
            for (int i = 0; i < 4; ++i) {
                __half h0 = __float2half(v[2*i]);
                __half h1 = __float2half(v[2*i+1]);
                hp[i] = (uint32_t)__half_as_ushort(h0) |
                        ((uint32_t)__half_as_ushort(h1) << 16);
            }
            uint32_t off = (uint32_t)(d0 >> 6) * 8192u + rowbase +
                           (((uint32_t)(d0 & 63) * 2u) ^ rx);
            *(uint4*)(smem + SM_XHI + off) = make_uint4(hp[0], hp[1], hp[2], hp[3]);
        }
    }

    // A-side ldmatrix constants (2 x 16x16 tiles over this warp's 32 rows)
    uint32_t aOff[2], aXor[2];
    #pragma unroll
    for (int mt = 0; mt < 2; ++mt) {
        int r = wm * 32 + mt * 16 + (lane & 7) + ((lane >> 3) & 1) * 8;
        aOff[mt] = (uint32_t)((r >> 3) * 1024 + (r & 7) * 128);
        aXor[mt] = (uint32_t)((r & 7) << 4);
    }
    const uint32_t adB = (lane >> 4) ? 16u : 0u;
    // B-side: 4 paired ldsm4 -> 8 n-tiles of 8 codes (warp covers 64 codes)
    uint32_t bpOff[4], bpXor[4];
    #pragma unroll
    for (int p = 0; p < 4; ++p) {
        int n = wn * 64 + p * 16 + ((lane >> 4) << 3) + (lane & 7);
        bpOff[p] = (uint32_t)((n >> 3) * 1024 + (n & 7) * 128);
        bpXor[p] = (uint32_t)((n & 7) << 4);
    }
    const uint32_t kB = (uint32_t)(((lane >> 3) & 1) << 4);

    float m1r[4], m2r[4]; int i1r[4];
    #pragma unroll
    for (int s = 0; s < 4; ++s) { m1r[s] = 3.4e38f; m2r[s] = 3.4e38f; i1r[s] = 0; }

    float acc[2][8][4];

    for (int seg = 0; seg < 16; ++seg) {        // seg = pass*4 + dchunk
        const int ch = seg & 3;
        // Hazard-safe single barrier: WAIT0 completes the group staged last
        // seg; the barrier (a) makes it visible to all warps and (b) orders
        // all of last seg's reads BEFORE this seg's cp.async overwrites.
        CP_WAIT0();
        __syncthreads();
        if (seg < 15) {
            const int ns = seg + 1;
            stage_B256(sb + SM_E + (uint32_t)(ns & 1) * 32768u,
                       g_eh + (size_t)(ns >> 2) * 256 * D_ + (ns & 3) * 64, tid);
        }

        if (ch == 0) {
            #pragma unroll
            for (int mt = 0; mt < 2; ++mt)
                #pragma unroll
                for (int nt = 0; nt < 8; ++nt)
                    #pragma unroll
                    for (int q = 0; q < 4; ++q) acc[mt][nt][q] = 0.f;
        }

        const uint32_t eh  = sb + SM_E + (uint32_t)(seg & 1) * 32768u;
        const uint32_t xco = (uint32_t)ch * 8192u;

        #pragma unroll
        for (int ks = 0; ks < 4; ++ks) {
            const uint32_t ksl = (uint32_t)ks * 32u;
            const uint32_t dA  = ksl + adB;
            uint32_t bh[8][2], ah[2][4];
            #pragma unroll
            for (int p = 0; p < 4; ++p) {
                uint32_t r4[4];
                ldsm4(r4, eh + bpOff[p] + ((ksl + kB) ^ bpXor[p]));
                bh[2*p][0] = r4[0]; bh[2*p][1] = r4[1];
                bh[2*p+1][0] = r4[2]; bh[2*p+1][1] = r4[3];
            }
            #pragma unroll
            for (int mt = 0; mt < 2; ++mt)
                ldsm4(ah[mt], sb + SM_XHI + xco + aOff[mt] + (dA ^ aXor[mt]));
            #pragma unroll
            for (int mt = 0; mt < 2; ++mt)
                #pragma unroll
                for (int nt = 0; nt < 8; ++nt)
                    mma16816(acc[mt][nt], ah[mt], bh[nt]);
        }

        if (ch == 3) {
            // fold scores: s = Se + dot (Sx dropped: rank-invariant; fixup
            // recomputes the exact reference formula for near-ties)
            const int pass = seg >> 2;
            const int cbase = pass * 256 + wn * 64 + 2 * (lane & 3);
            #pragma unroll
            for (int nt = 0; nt < 8; ++nt) {
                const int code0 = cbase + nt * 8;
                const float se0 = sSe[code0], se1 = sSe[code0 + 1];
                #pragma unroll
                for (int mt = 0; mt < 2; ++mt) {
                    const int s0 = mt * 2, s1 = mt * 2 + 1;
                    float v;
                    v = se0 + acc[mt][nt][0];
                    if (v < m1r[s0]) { m2r[s0] = m1r[s0]; m1r[s0] = v; i1r[s0] = code0; }
                    else if (v < m2r[s0]) m2r[s0] = v;
                    v = se1 + acc[mt][nt][1];
                    if (v < m1r[s0]) { m2r[s0] = m1r[s0]; m1r[s0] = v; i1r[s0] = code0 + 1; }
                    else if (v < m2r[s0]) m2r[s0] = v;
                    v = se0 + acc[mt][nt][2];
                    if (v < m1r[s1]) { m2r[s1] = m1r[s1]; m1r[s1] = v; i1r[s1] = code0; }
                    else if (v < m2r[s1]) m2r[s1] = v;
                    v = se1 + acc[mt][nt][3];
                    if (v < m1r[s1]) { m2r[s1] = m1r[s1]; m1r[s1] = v; i1r[s1] = code0 + 1; }
                    else if (v < m2r[s1]) m2r[s1] = v;
                }
            }
        }
    }

    __syncthreads();
    #pragma unroll
    for (int s = 0; s < 4; ++s) {
        float a1 = m1r[s], a2 = m2r[s]; int ai = i1r[s];
        #pragma unroll
        for (int ofs = 1; ofs <= 2; ofs <<= 1) {
            float v1 = __shfl_xor_sync(0xffffffffu, a1, ofs);
            float v2 = __shfl_xor_sync(0xffffffffu, a2, ofs);
            int   vi = __shfl_xor_sync(0xffffffffu, ai, ofs);
            if (v1 < a1 || (v1 == a1 && vi < ai)) { a2 = fminf(a1, v2); a1 = v1; ai = vi; }
            else                                  { a2 = fminf(a2, v1); }
        }
        if ((lane & 3) == 0) {
            int pix = wm * 32 + (s >> 1) * 16 + (lane >> 2) + (s & 1) * 8;
            red[(pix * 4 + wn) * 3 + 0] = a1;
            red[(pix * 4 + wn) * 3 + 1] = a2;
            red[(pix * 4 + wn) * 3 + 2] = __int_as_float(ai);
        }
    }
    __syncthreads();

    if (tid < 64) {
        float a1 = red[(tid * 4) * 3], a2 = red[(tid * 4) * 3 + 1];
        int   ai = __float_as_int(red[(tid * 4) * 3 + 2]);
        #pragma unroll
        for (int q = 1; q < 4; ++q) {
            float v1 = red[(tid * 4 + q) * 3], v2 = red[(tid * 4 + q) * 3 + 1];
            int   vi = __float_as_int(red[(tid * 4 + q) * 3 + 2]);
            if (v1 < a1 || (v1 == a1 && vi < ai)) { a2 = fminf(a1, v2); a1 = v1; ai = vi; }
            else                                  { a2 = fminf(a2, v1); }
        }
        const int row = b * HW_ + c0 + tid;
        g_idx[row] = ai;
        if (a2 - a1 < THRESH) {
            int pos = atomicAdd(&g_fixn, 1);
            g_fixlist[pos] = row;
        }
    }
}

// ---------------- exact-fp32 fixup v2: 2 rows/thread, d-split x2 ------------
#define FX_SX   0
#define FX_ED   16448
#define FX_SSX  (FX_ED + 69632)
#define FX_ROWS (FX_SSX + 64)
#define FX_TOTAL (FX_ROWS + 64)

__global__ __launch_bounds__(256)
void fixup_kernel(const float* __restrict__ x, const float* __restrict__ emb) {
    extern __shared__ char fsm[];
    float* sx  = (float*)(fsm + FX_SX);    // [16][257]
    float* ed  = (float*)(fsm + FX_ED);    // [256][68]
    float* sSx = (float*)(fsm + FX_SSX);   // [16]
    int*   rws = (int*)(fsm + FX_ROWS);    // [16]

    const int n    = g_fixn;
    const int tid  = threadIdx.x;
    const int lane = tid & 31;
    const int w    = tid >> 5;
    const int tc   = lane & 15;            // 4 codes per cb
    const int dh   = lane >> 4;            // d half: [0,128) or [128,256)
    const int rA   = w, rB = w + 8;        // this warp's two rows
    const int d0   = dh * 128;

    for (int base = blockIdx.x * 16; base < n; base += gridDim.x * 16) {
        if (tid < 16) rws[tid] = (base + tid < n) ? g_fixlist[base + tid] : -1;
        __syncthreads();
        // stage x rows (coalesced over pixels via strided d walk)
        for (int i = tid; i < 16 * D_; i += 256) {
            int rr = i >> 8, d = i & 255;
            int row = rws[rr];
            int row_c = (row < 0) ? 0 : row;
            int bb = row_c >> 12, pix = row_c & 4095;
            sx[rr * 257 + d] = x[(size_t)bb * (D_ * HW_) + (size_t)d * HW_ + pix];
        }
        __syncthreads();
        if (tid < 16) {   // ascending serial Sx (reference order)
            float s = 0.f;
            const float* xr = sx + tid * 257;
            for (int d = 0; d < D_; ++d) { float v = xr[d]; s = fmaf(v, v, s); }
            sSx[tid] = s;
        }

        float mA = 3.4e38f, mB = 3.4e38f;
        int   biA = 0, biB = 0;

        for (int cb = 0; cb < 16; ++cb) {
            __syncthreads();   // also covers the sSx writes on cb==0
            {   // stage 64 codes transposed: ed[d][cc]
                int cc = tid >> 2, dseg = (tid & 3) * 64;
                const float* er = emb + (size_t)(cb * 64 + cc) * D_ + dseg;
                for (int i = 0; i < 64; i += 4) {
                    float4 v = *(const float4*)(er + i);
                    ed[(dseg + i)     * 68 + cc] = v.x;
                    ed[(dseg + i + 1) * 68 + cc] = v.y;
                    ed[(dseg + i + 2) * 68 + cc] = v.z;
                    ed[(dseg + i + 3) * 68 + cc] = v.w;
                }
            }
            __syncthreads();
            // serial ascending fmaf over this thread's 128-d half, 2 rows x 4 codes
            float a0A = 0.f, a1A = 0.f, a2A = 0.f, a3A = 0.f;
            float a0B = 0.f, a1B = 0.f, a2B = 0.f, a3B = 0.f;
            const float* xrA = sx + rA * 257 + d0;
            const float* xrB = sx + rB * 257 + d0;
            const float* edp = ed + d0 * 68 + tc * 4;
            for (int d = 0; d < 128; ++d) {
                float4 ev = *(const float4*)(edp + d * 68);
                float xa = xrA[d], xb = xrB[d];
                a0A = fmaf(ev.x, xa, a0A); a1A = fmaf(ev.y, xa, a1A);
                a2A = fmaf(ev.z, xa, a2A); a3A = fmaf(ev.w, xa, a3A);
                a0B = fmaf(ev.x, xb, a0B); a1B = fmaf(ev.y, xb, a1B);
                a2B = fmaf(ev.z, xb, a2B); a3B = fmaf(ev.w, xb, a3B);
            }
            // combine the two d-halves (lane ^ 16 holds the partner partial)
            float pA[4] = {a0A, a1A, a2A, a3A};
            float pB[4] = {a0B, a1B, a2B, a3B};
            const float SxA = sSx[rA], SxB = sSx[rB];
            #pragma unroll
            for (int j = 0; j < 4; ++j) {
                float tA = pA[j] + __shfl_xor_sync(0xffffffffu, pA[j], 16);
                float tB = pB[j] + __shfl_xor_sync(0xffffffffu, pB[j], 16);
                int code = cb * 64 + tc * 4 + j;
                float en = g_enorm[code];
                float vA = fmaf(-2.f, tA, SxA + en);   // reference formula
                float vB = fmaf(-2.f, tB, SxB + en);
                if (vA < mA) { mA = vA; biA = code; }
                if (vB < mB) { mB = vB; biB = code; }
            }
        }
        // full-warp argmin reduce (dh halves hold identical values: harmless)
        #pragma unroll
        for (int ofs = 1; ofs <= 16; ofs <<= 1) {
            float ovA = __shfl_xor_sync(0xffffffffu, mA, ofs);
            int   oiA = __shfl_xor_sync(0xffffffffu, biA, ofs);
            if (ovA < mA || (ovA == mA && oiA < biA)) { mA = ovA; biA = oiA; }
            float ovB = __shfl_xor_sync(0xffffffffu, mB, ofs);
            int   oiB = __shfl_xor_sync(0xffffffffu, biB, ofs);
            if (ovB < mB || (ovB == mB && oiB < biB)) { mB = ovB; biB = oiB; }
        }
        if (lane == 0) {
            if (rws[rA] >= 0) g_idx[rws[rA]] = biA;
            if (rws[rB] >= 0) g_idx[rws[rB]] = biB;
        }
        __syncthreads();
    }
}

// ---------------- gather: 64-d chunks, MLP-8 batched loads, scalar stores ----
#define G_SIDX  0
#define G_WS    512
#define G_ET    1024                       // et[d][pixel], 64 x 132 floats
#define G_TOTAL (G_ET + 64 * 132 * 4)

__global__ __launch_bounds__(256)
void gather_kernel(const float* __restrict__ x, const float* __restrict__ emb,
                   float* __restrict__ outT) {
    extern __shared__ char gsm[];
    int*   sidx = (int*)(gsm + G_SIDX);
    float* ws   = (float*)(gsm + G_WS);
    float* et   = (float*)(gsm + G_ET);

    const int tid = threadIdx.x;
    const int b   = blockIdx.y;
    const int c0  = blockIdx.x * 128;
    if (tid < 128) sidx[tid] = g_idx[b * HW_ + c0 + tid];
    __syncthreads();

    const int pg = (tid & 31) * 4;     // 4-pixel group within warp
    const int dg = tid >> 5;           // warp -> 8 d rows per 64-d chunk
    float lsum = 0.f;

    for (int d0 = 0; d0 < D_; d0 += 64) {
        if (d0) __syncthreads();
        #pragma unroll
        for (int i = 0; i < 8; ++i) {
            int idx = tid + i * 256;
            int p = idx & 127, f4 = idx >> 7;
            float4 v = *(const float4*)(emb + (size_t)sidx[p] * D_ + d0 + f4 * 4);
            et[(f4 * 4 + 0) * 132 + p] = v.x;
            et[(f4 * 4 + 1) * 132 + p] = v.y;
            et[(f4 * 4 + 2) * 132 + p] = v.z;
            et[(f4 * 4 + 3) * 132 + p] = v.w;
        }
        __syncthreads();
        // batch ALL 8 x loads first (MLP=8), then compute + scalar stores
        const size_t base0 = (size_t)b * (D_ * HW_) + (size_t)(d0 + dg * 8) * HW_ + c0 + pg;
        float4 xv[8];
        #pragma unroll
        for (int j = 0; j < 8; ++j)
            xv[j] = *(const float4*)(x + base0 + (size_t)j * HW_);
        #pragma unroll
        for (int j = 0; j < 8; ++j) {
            float4 q = *(const float4*)(et + (dg * 8 + j) * 132 + pg);
            float dx0 = q.x - xv[j].x, dx1 = q.y - xv[j].y;
            float dx2 = q.z - xv[j].z, dx3 = q.w - xv[j].w;
            lsum = fmaf(dx0, dx0, lsum); lsum = fmaf(dx1, dx1, lsum);
            lsum = fmaf(dx2, dx2, lsum); lsum = fmaf(dx3, dx3, lsum);
            float* op = outT + base0 + (size_t)j * HW_;   // 4B-aligned: scalar STG
            op[0] = xv[j].x + dx0;                        // STE: fl(x + fl(q - x))
            op[1] = xv[j].y + dx1;
            op[2] = xv[j].z + dx2;
            op[3] = xv[j].w + dx3;
        }
    }
    #pragma unroll
    for (int o = 16; o; o >>= 1) lsum += __shfl_down_sync(0xffffffffu, lsum, o);
    if ((tid & 31) == 0) ws[tid >> 5] = lsum;
    __syncthreads();
    if (tid == 0) {
        float s = 0.f;
        #pragma unroll
        for (int i = 0; i < 8; ++i) s += ws[i];
        g_bsum[blockIdx.y * 32 + blockIdx.x] = s;
    }
}

// ---------------- loss finalize --------------------------------------------
__global__ void finalize_kernel(const float* beta, float* out) {
    __shared__ float sh[256];
    int tid = threadIdx.x;
    float s = 0.f;
    for (int i = tid; i < 1024; i += 256) s += g_bsum[i];
    sh[tid] = s; __syncthreads();
    for (int o = 128; o; o >>= 1) {
        if (tid < o) sh[tid] += sh[tid + o];
        __syncthreads();
    }
    if (tid == 0) {
        float bv = 0.25f;
        if (beta) {
            float f = *beta;
            if (f > 0.0f && f < 100.0f) bv = f;
            else {
                double dv = *(const double*)beta;
                if (dv > 0.0 && dv < 100.0) bv = (float)dv;
            }
        }
        out[0] = (1.0f + bv) * (sh[0] / 33554432.0f);
    }
}

// ---------------------------------------------------------------------------
extern "C" void kernel_launch(void* const* d_in, const int* in_sizes, int n_in,
                              void* d_out, int out_size) {
    (void)in_sizes;
    const float* x    = (const float*)d_in[0];
    const float* emb  = (const float*)d_in[1];
    const float* beta = (n_in > 2) ? (const float*)d_in[2] : nullptr;
    float* out = (float*)d_out;

    int off = out_size - TENSOR_ELEMS;
    if (off < 0) off = 0;

    cudaFuncSetAttribute(argmin_kernel,
                         cudaFuncAttributeMaxDynamicSharedMemorySize, SM_TOTAL);
    cudaFuncSetAttribute(fixup_kernel,
                         cudaFuncAttributeMaxDynamicSharedMemorySize, FX_TOTAL);
    cudaFuncSetAttribute(gather_kernel,
                         cudaFuncAttributeMaxDynamicSharedMemorySize, G_TOTAL);

    prep_kernel<<<K_, 256>>>(emb);
    dummy_kernel<<<1, 32>>>();              // keep ncu window on argmin
    dummy_kernel<<<1, 32>>>();
    argmin_kernel<<<2048, 256, SM_TOTAL>>>(x);
    fixup_kernel<<<256, 256, FX_TOTAL>>>(x, emb);
    gather_kernel<<<dim3(32, 32), 256, G_TOTAL>>>(x, emb, out + off);
    if (off >= 1) finalize_kernel<<<1, 256>>>(beta, out);
}